// round 9
// baseline (speedup 1.0000x reference)
#include <cuda_runtime.h>

// EpochedFutureFill == causal FIR conv, B=256, T=L=65536, via FFT of N=131072.
// Four-step decomposition: N = 256 (n1, stride 512) x 512 (n2, contiguous).
//   K0 : build twiddle tables (K1/K4 only)
//   K1 : pack + FFT256 over n1 (strided) + w_N^{-n2 k1}  -> U[k1][n2]
//   K2f: filter row: warp-FFT512 -> F (slot layout, scaled 1/N)
//   K23: warp-autonomous FFT512 fwd + multiply + IFFT512 + w_N^{+n2 k1} (in place)
//   K4 : IFFT256 over k1 (strided) + causal unpack to y
// Warp FFT uses in-place radix-4^2 dft16 (no register-transpose array -> no spills).
// Ordering conventions (verified):
//   dft16_dif: natural input  -> slot m holds X[DR16(m)]
//   dft16_dit: slot m holds in[DR16(m)] -> NATURAL output (slot m holds X[m])

namespace {
constexpr int N_FFT = 131072;
constexpr int T_LEN = 65536;
constexpr int PAIRS = 128;
constexpr int ROWS_F = 129;
constexpr float TWO_PI = 6.28318530717958647692f;
constexpr float INV_N = 1.0f / (float)N_FFT;
constexpr float W32C = 0.98078528040323044913f;   // cos(2pi/32)
constexpr float W32S = -0.19509032201612826785f;  // -sin(2pi/32)
}

// digit-reverse for radix-4^2 of 16: slot(p) = ((p&3)<<2)|(p>>2)  (involution)
#define DR16(p) ((((p) & 3) << 2) | ((p) >> 2))

// Scratch (no cudaMalloc allowed).
__device__ float2 g_buf[(size_t)ROWS_F * N_FFT];
__device__ float4 g_fspec4[N_FFT / 2];  // F in per-lane-contiguous slot layout
__device__ float2 g_t64[8 * 8];
__device__ float2 g_t256[4 * 64];

__device__ __forceinline__ float2 cadd(float2 a, float2 b) { return make_float2(a.x + b.x, a.y + b.y); }
__device__ __forceinline__ float2 csub(float2 a, float2 b) { return make_float2(a.x - b.x, a.y - b.y); }
__device__ __forceinline__ float2 cmul(float2 a, float2 b) {
    return make_float2(fmaf(a.x, b.x, -a.y * b.y), fmaf(a.x, b.y, a.y * b.x));
}
__device__ __forceinline__ float2 cmulc(float2 a, float2 b) {  // a * conj(b)
    return make_float2(fmaf(a.x, b.x, a.y * b.y), fmaf(a.y, b.x, -a.x * b.y));
}
template <int DIR>
__device__ __forceinline__ float2 cmuli(float2 a) {  // * (i*DIR)
    return (DIR < 0) ? make_float2(a.y, -a.x) : make_float2(-a.y, a.x);
}

template <int DIR>
__device__ __forceinline__ void dft4(float2 v[4]) {
    float2 t0 = cadd(v[0], v[2]);
    float2 t1 = cadd(v[1], v[3]);
    float2 t2 = csub(v[0], v[2]);
    float2 t3 = cmuli<DIR>(csub(v[1], v[3]));
    v[0] = cadd(t0, t1);
    v[2] = csub(t0, t1);
    v[1] = cadd(t2, t3);
    v[3] = csub(t2, t3);
}

template <int DIR>
__device__ __forceinline__ void dft8(float2 v[8]) {
    const float C = 0.70710678118654752440f;
    float2 b[4], d[4];
#pragma unroll
    for (int i = 0; i < 4; i++) {
        b[i] = cadd(v[i], v[i + 4]);
        d[i] = csub(v[i], v[i + 4]);
    }
    d[1] = cmul(d[1], make_float2(C, (float)DIR * C));
    d[2] = cmuli<DIR>(d[2]);
    d[3] = cmul(d[3], make_float2(-C, (float)DIR * C));
    dft4<DIR>(b);
    dft4<DIR>(d);
    v[0] = b[0]; v[2] = b[1]; v[4] = b[2]; v[6] = b[3];
    v[1] = d[0]; v[3] = d[1]; v[5] = d[2]; v[7] = d[3];
}

// In-place DIF radix-4^2 16-pt DFT. Input natural; output: slot m holds X[DR16(m)].
template <int DIR>
__device__ __forceinline__ void dft16_dif(float2 v[16]) {
    const float C1 = 0.92387953251128674f, S1 = 0.38268343236508978f;
    const float C2 = 0.70710678118654752f;
    const float D = (float)DIR;
    const float2 w1 = make_float2(C1, D * S1), w2 = make_float2(C2, D * C2);
    const float2 w3 = make_float2(S1, D * C1), w6 = make_float2(-C2, D * C2);
    const float2 w9 = make_float2(-C1, -D * S1);
#pragma unroll
    for (int j = 0; j < 4; j++) {
        float2 a[4] = {v[j], v[j + 4], v[j + 8], v[j + 12]};
        dft4<DIR>(a);
        if (j == 1) { a[1] = cmul(a[1], w1); a[2] = cmul(a[2], w2); a[3] = cmul(a[3], w3); }
        else if (j == 2) { a[1] = cmul(a[1], w2); a[2] = cmuli<DIR>(a[2]); a[3] = cmul(a[3], w6); }
        else if (j == 3) { a[1] = cmul(a[1], w3); a[2] = cmul(a[2], w6); a[3] = cmul(a[3], w9); }
        v[j] = a[0]; v[j + 4] = a[1]; v[j + 8] = a[2]; v[j + 12] = a[3];
    }
#pragma unroll
    for (int q = 0; q < 4; q++) {
        float2 a[4] = {v[4 * q], v[4 * q + 1], v[4 * q + 2], v[4 * q + 3]};
        dft4<DIR>(a);
        v[4 * q] = a[0]; v[4 * q + 1] = a[1]; v[4 * q + 2] = a[2]; v[4 * q + 3] = a[3];
    }
}

// In-place DIT radix-4^2 16-pt DFT. Input: slot m holds in[DR16(m)]. Output NATURAL.
template <int DIR>
__device__ __forceinline__ void dft16_dit(float2 v[16]) {
    const float C1 = 0.92387953251128674f, S1 = 0.38268343236508978f;
    const float C2 = 0.70710678118654752f;
    const float D = (float)DIR;
    const float2 w1 = make_float2(C1, D * S1), w2 = make_float2(C2, D * C2);
    const float2 w3 = make_float2(S1, D * C1), w6 = make_float2(-C2, D * C2);
    const float2 w9 = make_float2(-C1, -D * S1);
#pragma unroll
    for (int q = 0; q < 4; q++) {
        float2 a[4] = {v[4 * q], v[4 * q + 1], v[4 * q + 2], v[4 * q + 3]};
        dft4<DIR>(a);
        if (q == 1) { a[1] = cmul(a[1], w1); a[2] = cmul(a[2], w2); a[3] = cmul(a[3], w3); }
        else if (q == 2) { a[1] = cmul(a[1], w2); a[2] = cmuli<DIR>(a[2]); a[3] = cmul(a[3], w6); }
        else if (q == 3) { a[1] = cmul(a[1], w3); a[2] = cmul(a[2], w6); a[3] = cmul(a[3], w9); }
        v[4 * q] = a[0]; v[4 * q + 1] = a[1]; v[4 * q + 2] = a[2]; v[4 * q + 3] = a[3];
    }
#pragma unroll
    for (int u = 0; u < 4; u++) {
        float2 a[4] = {v[u], v[u + 4], v[u + 8], v[u + 12]};
        dft4<DIR>(a);
        v[u] = a[0]; v[u + 4] = a[1]; v[u + 8] = a[2]; v[u + 12] = a[3];
    }
}

__device__ __forceinline__ float2 shflx1(float2 a) {
    return make_float2(__shfl_xor_sync(0xffffffffu, a.x, 1),
                       __shfl_xor_sync(0xffffffffu, a.y, 1));
}

// ---------------- K0: build twiddle tables ----------------
__global__ void k_init_tables() {
    int i = threadIdx.x;
    if (i < 64) {
        int r = i >> 3, u = i & 7;
        float s, c;
        sincospif(-2.0f * (float)(r * u) / 64.0f, &s, &c);
        g_t64[i] = make_float2(c, s);
    }
    if (i < 256) {
        int m = i >> 6, j = i & 63;
        float s, c;
        sincospif(-2.0f * (float)(m * j) / 256.0f, &s, &c);
        g_t256[i] = make_float2(c, s);
    }
}

// ---------------- warp-level 512-pt forward FFT ----------------
// Entry: v[r] = u[lane + 32r]. Exit (slot layout): thread (p=lane>>1, h=lane&1)
// holds spectrum Y[p + 32*DR16(m) + 16*h] in v[m]. sw = 512-float2 warp smem.
__device__ __forceinline__ void wfft512_fwd(float2 v[16], float2* sw, int lane,
                                            float2 w512p, float2 w32p) {
    dft16_dif<-1>(v);  // slot m <-> freq DR16(m)
    int lo = lane & 15;
#pragma unroll
    for (int p = 0; p < 16; p++) sw[(lane << 4) + (p ^ lo)] = v[DR16(p)];
    __syncwarp();
    int p = lane >> 1, h = lane & 1;
#pragma unroll
    for (int j = 0; j < 16; j++) v[j] = sw[((16 * h + j) << 4) + (p ^ j)];
    __syncwarp();
    {   // twiddle w512^{p*(16h+j)} = (h? w32^p:1) * (w512^p)^j, chained over j
        float2 c = h ? w32p : make_float2(1.0f, 0.0f);
#pragma unroll
        for (int j = 0; j < 16; j++) { v[j] = cmul(v[j], c); c = cmul(c, w512p); }
    }
    {   // radix-2 butterfly over halves; w32^j chained
        float2 c32 = make_float2(1.0f, 0.0f);
        const float2 st = make_float2(W32C, W32S);
#pragma unroll
        for (int j = 0; j < 16; j++) {
            float2 other = shflx1(v[j]);
            if (h == 0) v[j] = cadd(v[j], other);
            else        v[j] = cmul(csub(other, v[j]), c32);
            c32 = cmul(c32, st);
        }
    }
    dft16_dif<-1>(v);  // slot m <-> q' = DR16(m)
}

// ---------------- K2f: filter spectrum in slot layout, scaled 1/N ----------------
__global__ __launch_bounds__(256, 4) void k_filter_spec(const float2* __restrict__ U,
                                                        float2* __restrict__ Fp) {
    __shared__ float2 sw[8][512];
    int lane = threadIdx.x & 31, w = threadIdx.x >> 5;
    int k1 = (blockIdx.x << 3) + w;
    int p = lane >> 1;
    float sA, cA, s0, c0;
    __sincosf(-(TWO_PI / 512.0f) * (float)p, &sA, &cA);
    __sincosf(-(TWO_PI / 32.0f) * (float)p, &s0, &c0);
    const float2* u = U + (size_t)PAIRS * N_FFT + (k1 << 9);
    float2 v[16];
#pragma unroll
    for (int r = 0; r < 16; r++) v[r] = u[lane + 32 * r];
    wfft512_fwd(v, sw[w], lane, make_float2(cA, sA), make_float2(c0, s0));
    // store slot-sequential: Fp[k1*512 + lane*16 + m]  (matches K23's multiply)
    float2* o = Fp + (k1 << 9) + (lane << 4);
#pragma unroll
    for (int m = 0; m < 16; m++)
        o[m] = make_float2(v[m].x * INV_N, v[m].y * INV_N);
}

// ---------------- K23: fwd FFT512 + multiply + inv FFT512 + w_N^{+n2 k1} ----------------
__global__ __launch_bounds__(256, 4) void k_stageB_conv(float2* U, const float4* __restrict__ Fp4) {
    __shared__ float2 sw[8][512];
    int lane = threadIdx.x & 31, w = threadIdx.x >> 5;
    int k1 = (blockIdx.x << 3) + w;
    int row = blockIdx.y;
    float2* u = U + (size_t)row * N_FFT + (k1 << 9);
    float2* s = sw[w];
    int p = lane >> 1, h = lane & 1;
    float sA, cA, s0, c0;
    __sincosf(-(TWO_PI / 512.0f) * (float)p, &sA, &cA);  // w512^p (fwd sign)
    __sincosf(-(TWO_PI / 32.0f) * (float)p, &s0, &c0);   // w32^p  (fwd sign)
    float2 w512p = make_float2(cA, sA), w32p = make_float2(c0, s0);

    float2 v[16];
#pragma unroll
    for (int r = 0; r < 16; r++) v[r] = u[lane + 32 * r];
    wfft512_fwd(v, s, lane, w512p, w32p);

    // multiply by filter spectrum (slot-aligned, 8 x LDG.128)
    const float4* Fr = Fp4 + (((k1 << 9) + (lane << 4)) >> 1);
#pragma unroll
    for (int m2 = 0; m2 < 8; m2++) {
        float4 f = __ldg(Fr + m2);
        v[2 * m2]     = cmul(v[2 * m2],     make_float2(f.x, f.y));
        v[2 * m2 + 1] = cmul(v[2 * m2 + 1], make_float2(f.z, f.w));
    }

    // ---- inverse ----
    dft16_dit<1>(v);  // digitrev in (slot m <-> q'=DR16(m)) -> NATURAL out: v[tau]
    {   // butterfly + conj twiddles, natural tau = j (+16h)
        float2 c32 = make_float2(1.0f, 0.0f);
        const float2 st32 = make_float2(W32C, W32S);
        float2 cB = h ? w32p : make_float2(1.0f, 0.0f);
#pragma unroll
        for (int j = 0; j < 16; j++) {
            float2 other = shflx1(v[j]);
            if (h == 0) v[j] = cadd(v[j], cmulc(other, c32));
            else        v[j] = csub(other, cmulc(v[j], c32));
            c32 = cmul(c32, st32);
            v[j] = cmulc(v[j], cB);
            cB = cmul(cB, w512p);
        }
    }
    __syncwarp();
#pragma unroll
    for (int j = 0; j < 16; j++) s[((j + 16 * h) << 4) + (p ^ j)] = v[j];
    __syncwarp();
    int lo = lane & 15;
#pragma unroll
    for (int q = 0; q < 16; q++) v[q] = s[(lane << 4) + (q ^ lo)];
    dft16_dif<1>(v);  // natural in -> slot m <-> r = DR16(m); n2 = lane + 32r

    // outer twiddle w_N^{+n2 k1}, iterate r natural over slots DR16(r)
    float sb, cb, ss, cs;
    __sincosf((TWO_PI / (float)N_FFT) * (float)(lane * k1), &sb, &cb);
    __sincosf((TWO_PI / 4096.0f) * (float)k1, &ss, &cs);  // w_N^{+32 k1}
    float2 wk = make_float2(cb, sb), wstep = make_float2(cs, ss);
#pragma unroll
    for (int r = 0; r < 16; r++) {
        u[lane + 32 * r] = cmul(v[DR16(r)], wk);
        wk = cmul(wk, wstep);
    }
}

// ---------------- K1: pack + FFT256 over n1 + w_N twiddle ----------------
__global__ __launch_bounds__(512) void k_stageA(const float* __restrict__ x,
                                                const float* __restrict__ filt,
                                                float2* __restrict__ U) {
    __shared__ float2 sm[256][16];
    int tx = threadIdx.x;
    int c = tx & 15, t = tx >> 4;
    int n2 = (blockIdx.x << 4) + c;
    int row = blockIdx.y;
    float2 v[8];
    if (row < PAIRS) {
        const float* xa = x + (size_t)row * T_LEN;
        const float* xb = x + (size_t)(row + PAIRS) * T_LEN;
#pragma unroll
        for (int r = 0; r < 4; r++) {
            int n = ((t + 32 * r) << 9) + n2;
            v[r] = make_float2(__ldg(xa + n), __ldg(xb + n));
        }
    } else {
#pragma unroll
        for (int r = 0; r < 4; r++) {
            int n = ((t + 32 * r) << 9) + n2;
            v[r] = make_float2(__ldg(filt + n), 0.0f);
        }
    }
#pragma unroll
    for (int r = 4; r < 8; r++) v[r] = make_float2(0.0f, 0.0f);

    dft8<-1>(v);
#pragma unroll
    for (int r = 0; r < 8; r++) sm[8 * t + r][c] = v[r];
    __syncthreads();
#pragma unroll
    for (int r = 0; r < 8; r++) v[r] = sm[t + 32 * r][c];
    {
        int t8 = t & 7;
#pragma unroll
        for (int r = 1; r < 8; r++) v[r] = cmul(v[r], __ldg(&g_t64[r * 8 + t8]));
    }
    dft8<-1>(v);
    __syncthreads();
    {
        int base = ((t >> 3) << 6) + (t & 7);
#pragma unroll
        for (int r = 0; r < 8; r++) sm[base + 8 * r][c] = v[r];
    }
    __syncthreads();

    float s64, c64;
    __sincosf(-(TWO_PI / 2048.0f) * (float)n2, &s64, &c64);
    float2 w64 = make_float2(c64, s64);
    float2* Ur = U + (size_t)row * N_FFT;
#pragma unroll
    for (int g = 0; g < 2; g++) {
        int j = t + 32 * g;
        float2 q[4];
#pragma unroll
        for (int m = 0; m < 4; m++) q[m] = sm[j + 64 * m][c];
#pragma unroll
        for (int m = 1; m < 4; m++) q[m] = cmul(q[m], __ldg(&g_t256[m * 64 + j]));
        dft4<-1>(q);
        float sb, cb;
        __sincosf(-(TWO_PI / (float)N_FFT) * (float)(n2 * j), &sb, &cb);
        float2 wk = make_float2(cb, sb);
#pragma unroll
        for (int m = 0; m < 4; m++) {
            int k1 = j + 64 * m;
            Ur[(k1 << 9) + n2] = cmul(q[m], wk);
            wk = cmul(wk, w64);
        }
    }
}

// ---------------- K4: IFFT256 over k1 + causal unpack ----------------
__global__ __launch_bounds__(512) void k_stageAinv(const float2* __restrict__ U,
                                                   float* __restrict__ y) {
    __shared__ float2 sm[256][16];
    int tx = threadIdx.x;
    int c = tx & 15, t = tx >> 4;
    int n2 = (blockIdx.x << 4) + c;
    int row = blockIdx.y;
    const float2* u = U + (size_t)row * N_FFT + n2;
    float2 v[8];
#pragma unroll
    for (int r = 0; r < 8; r++) v[r] = __ldg(u + (size_t)((t + 32 * r) << 9));
    dft8<1>(v);
#pragma unroll
    for (int r = 0; r < 8; r++) sm[8 * t + r][c] = v[r];
    __syncthreads();
#pragma unroll
    for (int r = 0; r < 8; r++) v[r] = sm[t + 32 * r][c];
    {
        int t8 = t & 7;
#pragma unroll
        for (int r = 1; r < 8; r++) v[r] = cmulc(v[r], __ldg(&g_t64[r * 8 + t8]));
    }
    dft8<1>(v);
    __syncthreads();
    {
        int base = ((t >> 3) << 6) + (t & 7);
#pragma unroll
        for (int r = 0; r < 8; r++) sm[base + 8 * r][c] = v[r];
    }
    __syncthreads();

    float* ya = y + (size_t)row * T_LEN;
    float* yb = y + (size_t)(row + PAIRS) * T_LEN;
#pragma unroll
    for (int g = 0; g < 2; g++) {
        int j = t + 32 * g;
        float2 q[4];
#pragma unroll
        for (int m = 0; m < 4; m++) q[m] = sm[j + 64 * m][c];
#pragma unroll
        for (int m = 1; m < 4; m++) q[m] = cmulc(q[m], __ldg(&g_t256[m * 64 + j]));
        dft4<1>(q);
#pragma unroll
        for (int m = 0; m < 2; m++) {
            int n = ((j + 64 * m) << 9) + n2;
            ya[n] = q[m].x;
            yb[n] = q[m].y;
        }
    }
}

extern "C" void kernel_launch(void* const* d_in, const int* in_sizes, int n_in,
                              void* d_out, int out_size) {
    const float* x = (const float*)d_in[0];
    const float* filt = (const float*)d_in[1];
    float* y = (float*)d_out;

    float2* U = nullptr;
    float4* F4 = nullptr;
    cudaGetSymbolAddress((void**)&U, g_buf);
    cudaGetSymbolAddress((void**)&F4, g_fspec4);

    k_init_tables<<<1, 512>>>();
    k_stageA<<<dim3(32, ROWS_F), 512>>>(x, filt, U);
    k_filter_spec<<<32, 256>>>(U, (float2*)F4);
    k_stageB_conv<<<dim3(32, PAIRS), 256>>>(U, F4);
    k_stageAinv<<<dim3(32, PAIRS), 512>>>(U, y);
}

// round 10
// speedup vs baseline: 1.0143x; 1.0143x over previous
#include <cuda_runtime.h>

// EpochedFutureFill == causal FIR conv, B=256, T=L=65536, via FFT of N=131072.
// Four-step decomposition: N = 256 (n1, stride 512) x 512 (n2, contiguous).
//   K0 : build twiddle tables (K1/K4 only)
//   K1 : pack + FFT256 over n1 (strided) + w_N^{-n2 k1}  -> U[k1][n2]
//   K2f: filter row: warp-FFT512 -> F (slot layout, scaled 1/N)
//   K23: warp-autonomous FFT512 fwd + multiply + IFFT512 + w_N^{+n2 k1} (in place)
//   K4 : IFFT256 over k1 (strided) + causal unpack to y
// R10: w32^j twiddles as compile-time constants (FFMA-imm), all 16-deep twiddle
// chains split into 2x8 (half the serial latency), smem swizzle includes the
// h-bit so both halves of each access phase hit disjoint banks.

namespace {
constexpr int N_FFT = 131072;
constexpr int T_LEN = 65536;
constexpr int PAIRS = 128;
constexpr int ROWS_F = 129;
constexpr float TWO_PI = 6.28318530717958647692f;
constexpr float INV_N = 1.0f / (float)N_FFT;
}

// digit-reverse for radix-4^2 of 16: slot(p) = ((p&3)<<2)|(p>>2)  (involution)
#define DR16(p) ((((p) & 3) << 2) | ((p) >> 2))

// Scratch (no cudaMalloc allowed).
__device__ float2 g_buf[(size_t)ROWS_F * N_FFT];
__device__ float4 g_fspec4[N_FFT / 2];  // F in per-lane-contiguous slot layout
__device__ float2 g_t64[8 * 8];
__device__ float2 g_t256[4 * 64];

__device__ __forceinline__ float2 cadd(float2 a, float2 b) { return make_float2(a.x + b.x, a.y + b.y); }
__device__ __forceinline__ float2 csub(float2 a, float2 b) { return make_float2(a.x - b.x, a.y - b.y); }
__device__ __forceinline__ float2 cmul(float2 a, float2 b) {
    return make_float2(fmaf(a.x, b.x, -a.y * b.y), fmaf(a.x, b.y, a.y * b.x));
}
__device__ __forceinline__ float2 cmulc(float2 a, float2 b) {  // a * conj(b)
    return make_float2(fmaf(a.x, b.x, a.y * b.y), fmaf(a.y, b.x, -a.x * b.y));
}
template <int DIR>
__device__ __forceinline__ float2 cmuli(float2 a) {  // * (i*DIR)
    return (DIR < 0) ? make_float2(a.y, -a.x) : make_float2(-a.y, a.x);
}

// exp(-2*pi*i*j/32), compile-time after unrolling -> FFMA-imm operands.
__device__ __forceinline__ float2 w32f(int j) {
    switch (j & 15) {
        case 0:  return make_float2(1.0f, 0.0f);
        case 1:  return make_float2(0.9807852804032304f, -0.19509032201612827f);
        case 2:  return make_float2(0.9238795325112868f, -0.3826834323650898f);
        case 3:  return make_float2(0.8314696123025452f, -0.5555702330196022f);
        case 4:  return make_float2(0.7071067811865476f, -0.7071067811865476f);
        case 5:  return make_float2(0.5555702330196022f, -0.8314696123025452f);
        case 6:  return make_float2(0.3826834323650898f, -0.9238795325112868f);
        case 7:  return make_float2(0.19509032201612827f, -0.9807852804032304f);
        case 8:  return make_float2(0.0f, -1.0f);
        case 9:  return make_float2(-0.19509032201612827f, -0.9807852804032304f);
        case 10: return make_float2(-0.3826834323650898f, -0.9238795325112868f);
        case 11: return make_float2(-0.5555702330196022f, -0.8314696123025452f);
        case 12: return make_float2(-0.7071067811865476f, -0.7071067811865476f);
        case 13: return make_float2(-0.8314696123025452f, -0.5555702330196022f);
        case 14: return make_float2(-0.9238795325112868f, -0.3826834323650898f);
        default: return make_float2(-0.9807852804032304f, -0.19509032201612827f);
    }
}

template <int DIR>
__device__ __forceinline__ void dft4(float2 v[4]) {
    float2 t0 = cadd(v[0], v[2]);
    float2 t1 = cadd(v[1], v[3]);
    float2 t2 = csub(v[0], v[2]);
    float2 t3 = cmuli<DIR>(csub(v[1], v[3]));
    v[0] = cadd(t0, t1);
    v[2] = csub(t0, t1);
    v[1] = cadd(t2, t3);
    v[3] = csub(t2, t3);
}

template <int DIR>
__device__ __forceinline__ void dft8(float2 v[8]) {
    const float C = 0.70710678118654752440f;
    float2 b[4], d[4];
#pragma unroll
    for (int i = 0; i < 4; i++) {
        b[i] = cadd(v[i], v[i + 4]);
        d[i] = csub(v[i], v[i + 4]);
    }
    d[1] = cmul(d[1], make_float2(C, (float)DIR * C));
    d[2] = cmuli<DIR>(d[2]);
    d[3] = cmul(d[3], make_float2(-C, (float)DIR * C));
    dft4<DIR>(b);
    dft4<DIR>(d);
    v[0] = b[0]; v[2] = b[1]; v[4] = b[2]; v[6] = b[3];
    v[1] = d[0]; v[3] = d[1]; v[5] = d[2]; v[7] = d[3];
}

// In-place DIF radix-4^2 16-pt DFT. Input natural; output: slot m holds X[DR16(m)].
template <int DIR>
__device__ __forceinline__ void dft16_dif(float2 v[16]) {
    const float C1 = 0.92387953251128674f, S1 = 0.38268343236508978f;
    const float C2 = 0.70710678118654752f;
    const float D = (float)DIR;
    const float2 w1 = make_float2(C1, D * S1), w2 = make_float2(C2, D * C2);
    const float2 w3 = make_float2(S1, D * C1), w6 = make_float2(-C2, D * C2);
    const float2 w9 = make_float2(-C1, -D * S1);
#pragma unroll
    for (int j = 0; j < 4; j++) {
        float2 a[4] = {v[j], v[j + 4], v[j + 8], v[j + 12]};
        dft4<DIR>(a);
        if (j == 1) { a[1] = cmul(a[1], w1); a[2] = cmul(a[2], w2); a[3] = cmul(a[3], w3); }
        else if (j == 2) { a[1] = cmul(a[1], w2); a[2] = cmuli<DIR>(a[2]); a[3] = cmul(a[3], w6); }
        else if (j == 3) { a[1] = cmul(a[1], w3); a[2] = cmul(a[2], w6); a[3] = cmul(a[3], w9); }
        v[j] = a[0]; v[j + 4] = a[1]; v[j + 8] = a[2]; v[j + 12] = a[3];
    }
#pragma unroll
    for (int q = 0; q < 4; q++) {
        float2 a[4] = {v[4 * q], v[4 * q + 1], v[4 * q + 2], v[4 * q + 3]};
        dft4<DIR>(a);
        v[4 * q] = a[0]; v[4 * q + 1] = a[1]; v[4 * q + 2] = a[2]; v[4 * q + 3] = a[3];
    }
}

// In-place DIT radix-4^2 16-pt DFT. Input: slot m holds in[DR16(m)]. Output NATURAL.
template <int DIR>
__device__ __forceinline__ void dft16_dit(float2 v[16]) {
    const float C1 = 0.92387953251128674f, S1 = 0.38268343236508978f;
    const float C2 = 0.70710678118654752f;
    const float D = (float)DIR;
    const float2 w1 = make_float2(C1, D * S1), w2 = make_float2(C2, D * C2);
    const float2 w3 = make_float2(S1, D * C1), w6 = make_float2(-C2, D * C2);
    const float2 w9 = make_float2(-C1, -D * S1);
#pragma unroll
    for (int q = 0; q < 4; q++) {
        float2 a[4] = {v[4 * q], v[4 * q + 1], v[4 * q + 2], v[4 * q + 3]};
        dft4<DIR>(a);
        if (q == 1) { a[1] = cmul(a[1], w1); a[2] = cmul(a[2], w2); a[3] = cmul(a[3], w3); }
        else if (q == 2) { a[1] = cmul(a[1], w2); a[2] = cmuli<DIR>(a[2]); a[3] = cmul(a[3], w6); }
        else if (q == 3) { a[1] = cmul(a[1], w3); a[2] = cmul(a[2], w6); a[3] = cmul(a[3], w9); }
        v[4 * q] = a[0]; v[4 * q + 1] = a[1]; v[4 * q + 2] = a[2]; v[4 * q + 3] = a[3];
    }
#pragma unroll
    for (int u = 0; u < 4; u++) {
        float2 a[4] = {v[u], v[u + 4], v[u + 8], v[u + 12]};
        dft4<DIR>(a);
        v[u] = a[0]; v[u + 4] = a[1]; v[u + 8] = a[2]; v[u + 12] = a[3];
    }
}

__device__ __forceinline__ float2 shflx1(float2 a) {
    return make_float2(__shfl_xor_sync(0xffffffffu, a.x, 1),
                       __shfl_xor_sync(0xffffffffu, a.y, 1));
}

// ---------------- K0: build twiddle tables ----------------
__global__ void k_init_tables() {
    int i = threadIdx.x;
    if (i < 64) {
        int r = i >> 3, u = i & 7;
        float s, c;
        sincospif(-2.0f * (float)(r * u) / 64.0f, &s, &c);
        g_t64[i] = make_float2(c, s);
    }
    if (i < 256) {
        int m = i >> 6, j = i & 63;
        float s, c;
        sincospif(-2.0f * (float)(m * j) / 256.0f, &s, &c);
        g_t256[i] = make_float2(c, s);
    }
}

// ---------------- warp-level 512-pt forward FFT ----------------
// Entry: v[r] = u[lane + 32r]. Exit (slot layout): thread (p=lane>>1, h=lane&1)
// holds spectrum Y[p + 32*DR16(m) + 16*h] in v[m]. sw = 512-float2 warp smem.
// w512p = exp(-2pi i p/512), w64p = w512p^8, w32p = w512p^16 (precomputed).
__device__ __forceinline__ void wfft512_fwd(float2 v[16], float2* sw, int lane,
                                            float2 w512p, float2 w64p, float2 w32p) {
    dft16_dif<-1>(v);  // slot m <-> freq DR16(m)
    int lo = lane & 15, hib = (lane >> 4) << 3;
#pragma unroll
    for (int p = 0; p < 16; p++) sw[(lane << 4) + (p ^ lo ^ hib)] = v[DR16(p)];
    __syncwarp();
    int p = lane >> 1, h = lane & 1;
#pragma unroll
    for (int j = 0; j < 16; j++) v[j] = sw[((16 * h + j) << 4) + (p ^ j ^ (h << 3))];
    __syncwarp();
    {   // twiddle w512^{p*(16h+j)}: two 8-deep chains (j and j+8)
        float2 c0 = h ? w32p : make_float2(1.0f, 0.0f);
        float2 c1 = cmul(c0, w64p);
#pragma unroll
        for (int j = 0; j < 8; j++) {
            v[j] = cmul(v[j], c0);
            v[j + 8] = cmul(v[j + 8], c1);
            c0 = cmul(c0, w512p);
            c1 = cmul(c1, w512p);
        }
    }
    {   // radix-2 butterfly over halves; w32^j are literals
#pragma unroll
        for (int j = 0; j < 16; j++) {
            float2 other = shflx1(v[j]);
            if (h == 0) v[j] = cadd(v[j], other);
            else if (j == 0) v[j] = csub(other, v[j]);
            else v[j] = cmul(csub(other, v[j]), w32f(j));
        }
    }
    dft16_dif<-1>(v);  // slot m <-> q' = DR16(m)
}

// ---------------- K2f: filter spectrum in slot layout, scaled 1/N ----------------
__global__ __launch_bounds__(256, 4) void k_filter_spec(const float2* __restrict__ U,
                                                        float2* __restrict__ Fp) {
    __shared__ float2 sw[8][512];
    int lane = threadIdx.x & 31, w = threadIdx.x >> 5;
    int k1 = (blockIdx.x << 3) + w;
    int p = lane >> 1;
    float sA, cA, s6, c6, s0, c0;
    __sincosf(-(TWO_PI / 512.0f) * (float)p, &sA, &cA);
    __sincosf(-(TWO_PI / 64.0f) * (float)p, &s6, &c6);
    __sincosf(-(TWO_PI / 32.0f) * (float)p, &s0, &c0);
    const float2* u = U + (size_t)PAIRS * N_FFT + (k1 << 9);
    float2 v[16];
#pragma unroll
    for (int r = 0; r < 16; r++) v[r] = u[lane + 32 * r];
    wfft512_fwd(v, sw[w], lane, make_float2(cA, sA), make_float2(c6, s6), make_float2(c0, s0));
    float2* o = Fp + (k1 << 9) + (lane << 4);
#pragma unroll
    for (int m = 0; m < 16; m++)
        o[m] = make_float2(v[m].x * INV_N, v[m].y * INV_N);
}

// ---------------- K23: fwd FFT512 + multiply + inv FFT512 + w_N^{+n2 k1} ----------------
__global__ __launch_bounds__(256, 4) void k_stageB_conv(float2* U, const float4* __restrict__ Fp4) {
    __shared__ float2 sw[8][512];
    int lane = threadIdx.x & 31, w = threadIdx.x >> 5;
    int k1 = (blockIdx.x << 3) + w;
    int row = blockIdx.y;
    float2* u = U + (size_t)row * N_FFT + (k1 << 9);
    float2* s = sw[w];
    int p = lane >> 1, h = lane & 1;
    float sA, cA, s6, c6, s0, c0;
    __sincosf(-(TWO_PI / 512.0f) * (float)p, &sA, &cA);  // w512^p (fwd sign)
    __sincosf(-(TWO_PI / 64.0f) * (float)p, &s6, &c6);   // w64^p = w512^{8p}
    __sincosf(-(TWO_PI / 32.0f) * (float)p, &s0, &c0);   // w32^p = w512^{16p}
    float2 w512p = make_float2(cA, sA), w64p = make_float2(c6, s6), w32p = make_float2(c0, s0);

    float2 v[16];
#pragma unroll
    for (int r = 0; r < 16; r++) v[r] = u[lane + 32 * r];
    wfft512_fwd(v, s, lane, w512p, w64p, w32p);

    // multiply by filter spectrum (slot-aligned, 8 x LDG.128)
    const float4* Fr = Fp4 + (((k1 << 9) + (lane << 4)) >> 1);
#pragma unroll
    for (int m2 = 0; m2 < 8; m2++) {
        float4 f = __ldg(Fr + m2);
        v[2 * m2]     = cmul(v[2 * m2],     make_float2(f.x, f.y));
        v[2 * m2 + 1] = cmul(v[2 * m2 + 1], make_float2(f.z, f.w));
    }

    // ---- inverse ----
    dft16_dit<1>(v);  // digitrev in (slot m <-> q'=DR16(m)) -> NATURAL out: v[tau]
    {   // butterfly (w32^j literals) + conj twiddle, two 8-deep cB chains
        float2 cB0 = h ? w32p : make_float2(1.0f, 0.0f);
        float2 cB1 = cmul(cB0, w64p);
#pragma unroll
        for (int j = 0; j < 8; j++) {
            {
                float2 other = shflx1(v[j]);
                if (h == 0) v[j] = (j == 0) ? cadd(v[j], other) : cadd(v[j], cmulc(other, w32f(j)));
                else        v[j] = (j == 0) ? csub(other, v[j]) : csub(other, cmulc(v[j], w32f(j)));
                v[j] = cmulc(v[j], cB0);
                cB0 = cmul(cB0, w512p);
            }
            {
                int j8 = j + 8;
                float2 other = shflx1(v[j8]);
                if (h == 0) v[j8] = cadd(v[j8], cmulc(other, w32f(j8)));
                else        v[j8] = csub(other, cmulc(v[j8], w32f(j8)));
                v[j8] = cmulc(v[j8], cB1);
                cB1 = cmul(cB1, w512p);
            }
        }
    }
    __syncwarp();
#pragma unroll
    for (int j = 0; j < 16; j++) s[((j + 16 * h) << 4) + (p ^ j ^ (h << 3))] = v[j];
    __syncwarp();
    int lo = lane & 15, hib = (lane >> 4) << 3;
#pragma unroll
    for (int q = 0; q < 16; q++) v[q] = s[(lane << 4) + (q ^ lo ^ hib)];
    dft16_dif<1>(v);  // natural in -> slot m <-> r = DR16(m); n2 = lane + 32r

    // outer twiddle w_N^{+n2 k1}: two 8-deep chains (r and r+8)
    float sb, cb, ss, cs, s8, c8;
    __sincosf((TWO_PI / (float)N_FFT) * (float)(lane * k1), &sb, &cb);
    __sincosf((TWO_PI / 4096.0f) * (float)k1, &ss, &cs);  // w_N^{+32 k1}
    __sincosf((TWO_PI / 512.0f) * (float)k1, &s8, &c8);   // w_N^{+256 k1}
    float2 wk0 = make_float2(cb, sb), wstep = make_float2(cs, ss);
    float2 wk8 = cmul(wk0, make_float2(c8, s8));
#pragma unroll
    for (int r = 0; r < 8; r++) {
        u[lane + 32 * r] = cmul(v[DR16(r)], wk0);
        u[lane + 32 * (r + 8)] = cmul(v[DR16(r + 8)], wk8);
        wk0 = cmul(wk0, wstep);
        wk8 = cmul(wk8, wstep);
    }
}

// ---------------- K1: pack + FFT256 over n1 + w_N twiddle ----------------
__global__ __launch_bounds__(512) void k_stageA(const float* __restrict__ x,
                                                const float* __restrict__ filt,
                                                float2* __restrict__ U) {
    __shared__ float2 sm[256][16];
    int tx = threadIdx.x;
    int c = tx & 15, t = tx >> 4;
    int n2 = (blockIdx.x << 4) + c;
    int row = blockIdx.y;
    float2 v[8];
    if (row < PAIRS) {
        const float* xa = x + (size_t)row * T_LEN;
        const float* xb = x + (size_t)(row + PAIRS) * T_LEN;
#pragma unroll
        for (int r = 0; r < 4; r++) {
            int n = ((t + 32 * r) << 9) + n2;
            v[r] = make_float2(__ldg(xa + n), __ldg(xb + n));
        }
    } else {
#pragma unroll
        for (int r = 0; r < 4; r++) {
            int n = ((t + 32 * r) << 9) + n2;
            v[r] = make_float2(__ldg(filt + n), 0.0f);
        }
    }
#pragma unroll
    for (int r = 4; r < 8; r++) v[r] = make_float2(0.0f, 0.0f);

    dft8<-1>(v);
#pragma unroll
    for (int r = 0; r < 8; r++) sm[8 * t + r][c] = v[r];
    __syncthreads();
#pragma unroll
    for (int r = 0; r < 8; r++) v[r] = sm[t + 32 * r][c];
    {
        int t8 = t & 7;
#pragma unroll
        for (int r = 1; r < 8; r++) v[r] = cmul(v[r], __ldg(&g_t64[r * 8 + t8]));
    }
    dft8<-1>(v);
    __syncthreads();
    {
        int base = ((t >> 3) << 6) + (t & 7);
#pragma unroll
        for (int r = 0; r < 8; r++) sm[base + 8 * r][c] = v[r];
    }
    __syncthreads();

    float s64, c64;
    __sincosf(-(TWO_PI / 2048.0f) * (float)n2, &s64, &c64);
    float2 w64 = make_float2(c64, s64);
    float2* Ur = U + (size_t)row * N_FFT;
#pragma unroll
    for (int g = 0; g < 2; g++) {
        int j = t + 32 * g;
        float2 q[4];
#pragma unroll
        for (int m = 0; m < 4; m++) q[m] = sm[j + 64 * m][c];
#pragma unroll
        for (int m = 1; m < 4; m++) q[m] = cmul(q[m], __ldg(&g_t256[m * 64 + j]));
        dft4<-1>(q);
        float sb, cb;
        __sincosf(-(TWO_PI / (float)N_FFT) * (float)(n2 * j), &sb, &cb);
        float2 wk = make_float2(cb, sb);
#pragma unroll
        for (int m = 0; m < 4; m++) {
            int k1 = j + 64 * m;
            Ur[(k1 << 9) + n2] = cmul(q[m], wk);
            wk = cmul(wk, w64);
        }
    }
}

// ---------------- K4: IFFT256 over k1 + causal unpack ----------------
__global__ __launch_bounds__(512) void k_stageAinv(const float2* __restrict__ U,
                                                   float* __restrict__ y) {
    __shared__ float2 sm[256][16];
    int tx = threadIdx.x;
    int c = tx & 15, t = tx >> 4;
    int n2 = (blockIdx.x << 4) + c;
    int row = blockIdx.y;
    const float2* u = U + (size_t)row * N_FFT + n2;
    float2 v[8];
#pragma unroll
    for (int r = 0; r < 8; r++) v[r] = __ldg(u + (size_t)((t + 32 * r) << 9));
    dft8<1>(v);
#pragma unroll
    for (int r = 0; r < 8; r++) sm[8 * t + r][c] = v[r];
    __syncthreads();
#pragma unroll
    for (int r = 0; r < 8; r++) v[r] = sm[t + 32 * r][c];
    {
        int t8 = t & 7;
#pragma unroll
        for (int r = 1; r < 8; r++) v[r] = cmulc(v[r], __ldg(&g_t64[r * 8 + t8]));
    }
    dft8<1>(v);
    __syncthreads();
    {
        int base = ((t >> 3) << 6) + (t & 7);
#pragma unroll
        for (int r = 0; r < 8; r++) sm[base + 8 * r][c] = v[r];
    }
    __syncthreads();

    float* ya = y + (size_t)row * T_LEN;
    float* yb = y + (size_t)(row + PAIRS) * T_LEN;
#pragma unroll
    for (int g = 0; g < 2; g++) {
        int j = t + 32 * g;
        float2 q[4];
#pragma unroll
        for (int m = 0; m < 4; m++) q[m] = sm[j + 64 * m][c];
#pragma unroll
        for (int m = 1; m < 4; m++) q[m] = cmulc(q[m], __ldg(&g_t256[m * 64 + j]));
        dft4<1>(q);
#pragma unroll
        for (int m = 0; m < 2; m++) {
            int n = ((j + 64 * m) << 9) + n2;
            ya[n] = q[m].x;
            yb[n] = q[m].y;
        }
    }
}

extern "C" void kernel_launch(void* const* d_in, const int* in_sizes, int n_in,
                              void* d_out, int out_size) {
    const float* x = (const float*)d_in[0];
    const float* filt = (const float*)d_in[1];
    float* y = (float*)d_out;

    float2* U = nullptr;
    float4* F4 = nullptr;
    cudaGetSymbolAddress((void**)&U, g_buf);
    cudaGetSymbolAddress((void**)&F4, g_fspec4);

    k_init_tables<<<1, 512>>>();
    k_stageA<<<dim3(32, ROWS_F), 512>>>(x, filt, U);
    k_filter_spec<<<32, 256>>>(U, (float2*)F4);
    k_stageB_conv<<<dim3(32, PAIRS), 256>>>(U, F4);
    k_stageAinv<<<dim3(32, PAIRS), 512>>>(U, y);
}